// round 4
// baseline (speedup 1.0000x reference)
#include <cuda_runtime.h>
#include <cuda_bf16.h>

// ---------------- problem constants ----------------
constexpr int N_CHR = 50000, E_CHR = 500000;
constexpr int N_SLV = 30000, E_SLV = 300000;
constexpr int NTOT = N_CHR + N_SLV;      // 80000
constexpr int ETOT = E_CHR + E_SLV;      // 800000
constexpr int B    = 256;
constexpr int FEAT = 64;
constexpr int DIM  = 128;
constexpr int HALF = 64;
constexpr int ENS  = 3;

// ---------------- scratch (device globals; no allocations allowed) --------
__device__ float g_aggx[(size_t)NTOT * FEAT];
__device__ float g_buf1[(size_t)NTOT * ENS * DIM];
__device__ float g_buf2[(size_t)NTOT * ENS * DIM];
__device__ float g_pool[(size_t)B * 2 * ENS * HALF];
__device__ int   g_deg[NTOT];        // ZERO at entry of every run (static init + tail-zero in gather64)
__device__ int   g_off[NTOT];
__device__ int   g_cursor[NTOT];     // after fill: end offset of each node
__device__ int   g_csr[ETOT];

// ---------------- f32x2 helpers ----------------
typedef unsigned long long ull;
__device__ __forceinline__ ull ffma2(ull a, ull b, ull c) {
    ull d;
    asm("fma.rn.f32x2 %0, %1, %2, %3;" : "=l"(d) : "l"(a), "l"(b), "l"(c));
    return d;
}
__device__ __forceinline__ void fadd2(ull& acc, ull v) {
    asm("add.rn.f32x2 %0, %0, %1;" : "+l"(acc) : "l"(v));
}
__device__ __forceinline__ void unpack2(ull v, float& lo, float& hi) {
    asm("mov.b64 {%0, %1}, %2;" : "=f"(lo), "=f"(hi) : "l"(v));
}

__device__ __forceinline__ void red_add_v4(float* p, float4 v) {
    asm volatile("red.global.add.v4.f32 [%0], {%1,%2,%3,%4};"
                 :: "l"(p), "f"(v.x), "f"(v.y), "f"(v.z), "f"(v.w)
                 : "memory");
}

__device__ __forceinline__ void edge_sd(int e, const int* __restrict__ ec,
                                        const int* __restrict__ es, int& src, int& dst) {
    if (e < E_CHR) { src = ec[e]; dst = ec[E_CHR + e]; }
    else { int e2 = e - E_CHR; src = N_CHR + es[e2]; dst = N_CHR + es[E_SLV + e2]; }
}

// ---------------- CSR build ----------------
// also zeroes g_pool (first 24576 threads); requires g_deg == 0 at entry.
__global__ void count_deg_kernel(const int* __restrict__ ec, const int* __restrict__ es) {
    int e = blockIdx.x * blockDim.x + threadIdx.x;
    if (e < B * 384 / 4) ((float4*)g_pool)[e] = make_float4(0.f, 0.f, 0.f, 0.f);
    if (e >= ETOT) return;
    int src, dst; edge_sd(e, ec, es, src, dst);
    atomicAdd(&g_deg[dst], 1);
}

// single-block exclusive scan of g_deg -> g_off, g_cursor
__global__ __launch_bounds__(1024)
void scan_block_kernel() {
    __shared__ int warpsum[32];
    __shared__ int s_carry;
    int tid = threadIdx.x, lane = tid & 31, wid = tid >> 5;
    if (tid == 0) s_carry = 0;
    __syncthreads();
    for (int c0 = 0; c0 < NTOT; c0 += 1024) {
        int carry = s_carry;
        int i = c0 + tid;
        int v = (i < NTOT) ? g_deg[i] : 0;
        int x = v;
        #pragma unroll
        for (int o = 1; o < 32; o <<= 1) {
            int t = __shfl_up_sync(0xffffffffu, x, o);
            if (lane >= o) x += t;
        }
        if (lane == 31) warpsum[wid] = x;
        __syncthreads();
        if (wid == 0) {
            int y = warpsum[lane];
            #pragma unroll
            for (int o = 1; o < 32; o <<= 1) {
                int t = __shfl_up_sync(0xffffffffu, y, o);
                if (lane >= o) y += t;
            }
            warpsum[lane] = y;
        }
        __syncthreads();
        int start = carry + (wid ? warpsum[wid - 1] : 0) + x - v;
        if (i < NTOT) { g_off[i] = start; g_cursor[i] = start; }
        __syncthreads();
        if (tid == 0) s_carry = carry + warpsum[31];
        __syncthreads();
    }
}

__global__ void fill_csr_kernel(const int* __restrict__ ec, const int* __restrict__ es) {
    int e = blockIdx.x * blockDim.x + threadIdx.x;
    if (e >= ETOT) return;
    int src, dst; edge_sd(e, ec, es, src, dst);
    int pos = atomicAdd(&g_cursor[dst], 1);
    g_csr[pos] = src;
}

// ---------------- gathers ----------------
// first aggregation over raw features (64 wide); 2 nodes per warp.
// Also tail-zeroes g_deg for the next run.
__global__ __launch_bounds__(256)
void gather64_kernel(const float* __restrict__ xchr, const float* __restrict__ xslv,
                     float* __restrict__ out) {
    int lane = threadIdx.x & 31;
    int sub = lane >> 4;
    int l = lane & 15;
    int hw = ((blockIdx.x * blockDim.x + threadIdx.x) >> 5) * 2 + sub;
    if (hw >= NTOT) return;
    int start = g_off[hw], deg = g_cursor[hw] - start;
    if (l == 0) g_deg[hw] = 0;
    ull a0 = 0, a1 = 0;
    for (int kb = 0; kb < deg; kb += 16) {
        int idx = (kb + l < deg) ? g_csr[start + kb + l] : 0;
        int m = min(16, deg - kb);
        for (int k = 0; k < m; k++) {
            int s = __shfl_sync(0xffffffffu, idx, k, 16);
            const ulonglong2* sr = (s < N_CHR) ? (const ulonglong2*)(xchr + (size_t)s * 64)
                                               : (const ulonglong2*)(xslv + (size_t)(s - N_CHR) * 64);
            ulonglong2 v = sr[l];
            fadd2(a0, v.x); fadd2(a1, v.y);
        }
    }
    ulonglong2 r; r.x = a0; r.y = a1;
    ((ulonglong2*)(out + (size_t)hw * 64))[l] = r;
}

// 384-wide aggregation: one warp per node
__global__ __launch_bounds__(256)
void gather384_kernel(const float* __restrict__ in, float* __restrict__ out) {
    int lane = threadIdx.x & 31;
    int w = (blockIdx.x * blockDim.x + threadIdx.x) >> 5;
    if (w >= NTOT) return;
    int start = g_off[w], deg = g_cursor[w] - start;
    ull a[6] = {0, 0, 0, 0, 0, 0};
    for (int kb = 0; kb < deg; kb += 32) {
        int idx = (kb + lane < deg) ? g_csr[start + kb + lane] : 0;
        int m = min(32, deg - kb);
        for (int k = 0; k < m; k++) {
            int s = __shfl_sync(0xffffffffu, idx, k);
            const ulonglong2* sr = (const ulonglong2*)(in + (size_t)s * 384);
            ulonglong2 v0 = sr[lane], v1 = sr[lane + 32], v2 = sr[lane + 64];
            fadd2(a[0], v0.x); fadd2(a[1], v0.y);
            fadd2(a[2], v1.x); fadd2(a[3], v1.y);
            fadd2(a[4], v2.x); fadd2(a[5], v2.y);
        }
    }
    ulonglong2* d = (ulonglong2*)(out + (size_t)w * 384);
    ulonglong2 r0; r0.x = a[0]; r0.y = a[1];
    ulonglong2 r1; r1.x = a[2]; r1.y = a[3];
    ulonglong2 r2; r2.x = a[4]; r2.y = a[5];
    d[lane] = r0; d[lane + 32] = r1; d[lane + 64] = r2;
}

// layer-2 aggregation fused with relu + global_add_pool (rows 192 wide)
__global__ __launch_bounds__(256)
void gather192_pool_kernel(const float* __restrict__ in,
                           const int* __restrict__ bchr, const int* __restrict__ bslv) {
    int lane = threadIdx.x & 31;
    int w = (blockIdx.x * blockDim.x + threadIdx.x) >> 5;
    if (w >= NTOT) return;
    int start = g_off[w], deg = g_cursor[w] - start;
    ull a[4] = {0, 0, 0, 0};
    for (int kb = 0; kb < deg; kb += 32) {
        int idx = (kb + lane < deg) ? g_csr[start + kb + lane] : 0;
        int m = min(32, deg - kb);
        for (int k = 0; k < m; k++) {
            int s = __shfl_sync(0xffffffffu, idx, k);
            const ulonglong2* sr = (const ulonglong2*)(in + (size_t)s * 192);
            ulonglong2 v0 = sr[lane];
            fadd2(a[0], v0.x); fadd2(a[1], v0.y);
            if (lane < 16) {
                ulonglong2 v1 = sr[lane + 32];
                fadd2(a[2], v1.x); fadd2(a[3], v1.y);
            }
        }
    }
    float4 f0, f1;
    unpack2(a[0], f0.x, f0.y); unpack2(a[1], f0.z, f0.w);
    unpack2(a[2], f1.x, f1.y); unpack2(a[3], f1.z, f1.w);
    f0.x = fmaxf(f0.x, 0.f); f0.y = fmaxf(f0.y, 0.f); f0.z = fmaxf(f0.z, 0.f); f0.w = fmaxf(f0.w, 0.f);
    f1.x = fmaxf(f1.x, 0.f); f1.y = fmaxf(f1.y, 0.f); f1.z = fmaxf(f1.z, 0.f); f1.w = fmaxf(f1.w, 0.f);
    int b, colbase;
    if (w < N_CHR) { b = bchr[w]; colbase = 0; }
    else           { b = bslv[w - N_CHR]; colbase = 192; }
    float* prow = g_pool + (size_t)b * 384 + colbase;
    red_add_v4(prow + lane * 4, f0);
    if (lane < 16) red_add_v4(prow + 128 + lane * 4, f1);
}

// ---------------- register-tiled GEMM with fma.rn.f32x2 -------------------
// out[n, e*out_eoff + j] = (relu?)( in[n, e*in_eoff + 0:K] @ W[e] )
// 256 threads; 8 rows x 8 cols per thread, rows packed in f32x2 pairs.
// Weights pre-duplicated (w,w) in smem; input tile stored transposed.
template<int K, int MOUT, bool RELU_IN, bool RELU_OUT>
__global__ __launch_bounds__(256, 1)
void gemm_kernel(const float* __restrict__ in, float* __restrict__ out,
                 const float* __restrict__ Wc, const float* __restrict__ Ws,
                 int in_stride, int in_eoff, int out_stride, int out_eoff) {
    constexpr int CG = MOUT / 8;        // col groups
    constexpr int RG = 256 / CG;        // row groups
    constexpr int TR = RG * 8;          // rows per tile
    constexpr int TRP = TR + 4;         // padded
    extern __shared__ float sm[];
    ull*   sW2  = (ull*)sm;             // [K][MOUT] duplicated pairs (8B each)
    float* sInT = sm + 2 * K * MOUT;    // [K][TRP] transposed input tile

    const int e = blockIdx.y;
    const int branch = blockIdx.z;
    const int tid = threadIdx.x;
    const int cgrp = tid % CG;
    const int rgrp = tid / CG;
    const int j0 = cgrp * 8;

    const int base  = branch ? N_CHR : 0;
    const int nrows = branch ? N_SLV : N_CHR;
    const int ntiles = (nrows + TR - 1) / TR;
    const float* W = (branch ? Ws : Wc) + (size_t)e * K * MOUT;

    for (int i = tid; i < K * MOUT; i += 256) {
        float v = W[i];
        float2 d; d.x = v; d.y = v;
        ((float2*)sW2)[i] = d;
    }
    __syncthreads();

    for (int t = blockIdx.x; t < ntiles; t += gridDim.x) {
        int row0 = base + t * TR;
        int rcnt = min(TR, base + nrows - row0);
        constexpr int C4 = TR * (K / 4);
        for (int i = tid; i < C4; i += 256) {
            int r = i / (K / 4), kc = i % (K / 4);
            float4 v = make_float4(0.f, 0.f, 0.f, 0.f);
            if (r < rcnt) {
                v = *(const float4*)(in + (size_t)(row0 + r) * in_stride + (size_t)e * in_eoff + kc * 4);
                if (RELU_IN) {
                    v.x = fmaxf(v.x, 0.f); v.y = fmaxf(v.y, 0.f);
                    v.z = fmaxf(v.z, 0.f); v.w = fmaxf(v.w, 0.f);
                }
            }
            int kk = kc * 4;
            sInT[(kk + 0) * TRP + r] = v.x;
            sInT[(kk + 1) * TRP + r] = v.y;
            sInT[(kk + 2) * TRP + r] = v.z;
            sInT[(kk + 3) * TRP + r] = v.w;
        }
        __syncthreads();

        ull acc[4][8];
        #pragma unroll
        for (int rp = 0; rp < 4; rp++)
            #pragma unroll
            for (int c = 0; c < 8; c++) acc[rp][c] = 0ull;

        #pragma unroll 4
        for (int k = 0; k < K; k++) {
            const ulonglong2* ap = (const ulonglong2*)(sInT + k * TRP + rgrp * 8);
            ulonglong2 A01 = ap[0], A23 = ap[1];
            ull a2[4] = {A01.x, A01.y, A23.x, A23.y};
            const ulonglong2* wp = (const ulonglong2*)(sW2 + (size_t)k * MOUT + j0);
            ulonglong2 W01 = wp[0], W23 = wp[1], W45 = wp[2], W67 = wp[3];
            ull ww[8] = {W01.x, W01.y, W23.x, W23.y, W45.x, W45.y, W67.x, W67.y};
            #pragma unroll
            for (int rp = 0; rp < 4; rp++)
                #pragma unroll
                for (int c = 0; c < 8; c++)
                    acc[rp][c] = ffma2(a2[rp], ww[c], acc[rp][c]);
        }

        #pragma unroll
        for (int rp = 0; rp < 4; rp++) {
            float lo[8], hi[8];
            #pragma unroll
            for (int c = 0; c < 8; c++) unpack2(acc[rp][c], lo[c], hi[c]);
            #pragma unroll
            for (int half = 0; half < 2; half++) {
                int rr = rgrp * 8 + 2 * rp + half;
                if (rr < rcnt) {
                    float* src = half ? hi : lo;
                    float* op = out + (size_t)(row0 + rr) * out_stride + (size_t)e * out_eoff + j0;
                    #pragma unroll
                    for (int c0 = 0; c0 < 8; c0 += 4) {
                        float4 v;
                        v.x = src[c0 + 0]; v.y = src[c0 + 1];
                        v.z = src[c0 + 2]; v.w = src[c0 + 3];
                        if (RELU_OUT) {
                            v.x = fmaxf(v.x, 0.f); v.y = fmaxf(v.y, 0.f);
                            v.z = fmaxf(v.z, 0.f); v.w = fmaxf(v.w, 0.f);
                        }
                        *(float4*)(op + c0) = v;
                    }
                }
            }
        }
        __syncthreads();
    }
}

// ---------------- head: projection heads + concat + fc1 + fc2 -------------
__global__ __launch_bounds__(128)
void head_kernel(const float* __restrict__ cfcW, const float* __restrict__ cfcb,
                 const float* __restrict__ sfcW, const float* __restrict__ sfcb,
                 const float* __restrict__ fc1W, const float* __restrict__ fc1b,
                 const float* __restrict__ fc2W, const float* __restrict__ fc2b,
                 float* __restrict__ out) {
    __shared__ float sPool[384];
    __shared__ float sHg[768];
    __shared__ float sRed[128];
    const int b = blockIdx.x;
    const int tid = threadIdx.x;

    for (int i = tid; i < 384; i += 128) sPool[i] = g_pool[(size_t)b * 384 + i];
    __syncthreads();

    #pragma unroll
    for (int p = 0; p < 6; p++) {
        const bool slv = (p >= 3);
        const int e = slv ? (p - 3) : p;
        const float* W = slv ? sfcW : cfcW;
        const float* bias = slv ? sfcb : cfcb;
        const float* rep = sPool + (slv ? 192 : 0) + e * HALF;
        float acc = bias[e * DIM + tid];
        #pragma unroll 8
        for (int k = 0; k < HALF; k++)
            acc = fmaf(rep[k], W[(size_t)e * HALF * DIM + k * DIM + tid], acc);
        sHg[p * DIM + tid] = fmaxf(acc, 0.f);
    }
    __syncthreads();

    float acc = fc1b[tid];
    #pragma unroll 8
    for (int h = 0; h < 768; h++)
        acc = fmaf(sHg[h], fc1W[(size_t)h * DIM + tid], acc);
    float o1 = fmaxf(acc, 0.f);

    sRed[tid] = o1 * fc2W[tid];
    __syncthreads();
    if (tid < 64) sRed[tid] += sRed[tid + 64];
    __syncthreads();
    if (tid < 32) {
        float x = sRed[tid] + sRed[tid + 32];
        #pragma unroll
        for (int o = 16; o; o >>= 1) x += __shfl_down_sync(0xffffffffu, x, o);
        if (tid == 0) out[b] = x + fc2b[0];
    }
}

// ---------------- launch ----------------
extern "C" void kernel_launch(void* const* d_in, const int* in_sizes, int n_in,
                              void* d_out, int out_size) {
    const float* chr_x  = (const float*)d_in[0];
    const float* slv_x  = (const float*)d_in[1];
    const int*   chr_ei = (const int*)d_in[2];
    const int*   slv_ei = (const int*)d_in[3];
    const int*   chr_b  = (const int*)d_in[4];
    const int*   slv_b  = (const int*)d_in[5];
    const float* chr_W0 = (const float*)d_in[6];
    const float* chr_W1 = (const float*)d_in[7];
    const float* chr_W2 = (const float*)d_in[8];
    const float* slv_W0 = (const float*)d_in[9];
    const float* slv_W1 = (const float*)d_in[10];
    const float* slv_W2 = (const float*)d_in[11];
    const float* cfcW   = (const float*)d_in[12];
    const float* cfcb   = (const float*)d_in[13];
    const float* sfcW   = (const float*)d_in[14];
    const float* sfcb   = (const float*)d_in[15];
    const float* fc1W   = (const float*)d_in[16];
    const float* fc1b   = (const float*)d_in[17];
    const float* fc2W   = (const float*)d_in[18];
    const float* fc2b   = (const float*)d_in[19];
    float* out = (float*)d_out;

    float *aggx, *buf1, *buf2;
    cudaGetSymbolAddress((void**)&aggx, g_aggx);
    cudaGetSymbolAddress((void**)&buf1, g_buf1);
    cudaGetSymbolAddress((void**)&buf2, g_buf2);

    // dynamic smem: sW2 (K*MOUT*8) + sInT (K*TRP*4)
    constexpr int SM0 = 64  * 128 * 8 + 64  * 132 * 4;  // 99328
    constexpr int SM1 = 128 * 128 * 8 + 128 * 132 * 4;  // 198656
    constexpr int SM2 = 128 * 64  * 8 + 128 * 260 * 4;  // 198656
    cudaFuncSetAttribute((const void*)gemm_kernel<64, 128, false, true>,
                         cudaFuncAttributeMaxDynamicSharedMemorySize, SM0);
    cudaFuncSetAttribute((const void*)gemm_kernel<128, 128, false, false>,
                         cudaFuncAttributeMaxDynamicSharedMemorySize, SM1);
    cudaFuncSetAttribute((const void*)gemm_kernel<128, 64, true, false>,
                         cudaFuncAttributeMaxDynamicSharedMemorySize, SM2);

    dim3 ggrid(148, ENS, 2);

    // ---- CSR build (g_deg is zero at entry; re-zeroed inside gather64) ----
    count_deg_kernel<<<(ETOT + 255) / 256, 256>>>(chr_ei, slv_ei);   // + pool zero
    scan_block_kernel<<<1, 1024>>>();
    fill_csr_kernel<<<(ETOT + 255) / 256, 256>>>(chr_ei, slv_ei);

    // ---- forward pass ----
    // 1) aggx = A x   (shared across ensembles, 64 wide)
    gather64_kernel<<<(NTOT / 2 + 7) / 8, 256>>>(chr_x, slv_x, aggx);
    // 2) h0 = relu(aggx @ W0) -> buf1 [N, 3*128]
    gemm_kernel<64, 128, false, true><<<ggrid, 256, SM0>>>(
        aggx, buf1, chr_W0, slv_W0, FEAT, 0, ENS * DIM, DIM);
    // 3) t1 = h0 @ W1 -> buf2
    gemm_kernel<128, 128, false, false><<<ggrid, 256, SM1>>>(
        buf1, buf2, chr_W1, slv_W1, ENS * DIM, DIM, ENS * DIM, DIM);
    // 4) agg1 = A t1 -> buf1
    gather384_kernel<<<NTOT / 8, 256>>>(buf2, buf1);
    // 5) t2 = relu(agg1) @ W2 -> buf2 [N, 3*64]
    gemm_kernel<128, 64, true, false><<<ggrid, 256, SM2>>>(
        buf1, buf2, chr_W2, slv_W2, ENS * DIM, DIM, ENS * HALF, HALF);
    // 6) pool[batch] += relu(A t2)   (fused aggregation + relu + pool)
    gather192_pool_kernel<<<NTOT / 8, 256>>>(buf2, chr_b, slv_b);
    // 7) head
    head_kernel<<<B, 128>>>(cfcW, cfcb, sfcW, sfcb, fc1W, fc1b, fc2W, fc2b, out);
}

// round 5
// speedup vs baseline: 1.8851x; 1.8851x over previous
#include <cuda_runtime.h>
#include <cuda_bf16.h>
#include <cuda_fp16.h>

// ---------------- problem constants ----------------
constexpr int N_CHR = 50000, E_CHR = 500000;
constexpr int N_SLV = 30000, E_SLV = 300000;
constexpr int NTOT = N_CHR + N_SLV;      // 80000
constexpr int ETOT = E_CHR + E_SLV;      // 800000
constexpr int B    = 256;
constexpr int FEAT = 64;
constexpr int DIM  = 128;
constexpr int HALF = 64;
constexpr int ENS  = 3;
constexpr int SCAN_BLK = 1024;
constexpr int NB_SCAN = (NTOT + SCAN_BLK - 1) / SCAN_BLK;  // 79

// ---------------- scratch (device globals; no allocations allowed) --------
__device__ float g_aggx[(size_t)NTOT * FEAT];
__device__ float g_buf1[(size_t)NTOT * ENS * DIM];
__device__ float g_buf2[(size_t)NTOT * ENS * DIM];   // also reused as __half buffer
__device__ float g_pool[(size_t)B * 2 * ENS * HALF];
__device__ int   g_deg[NTOT];        // ZERO at entry of every run (static init + re-zero in gather64)
__device__ int   g_incl[NTOT];
__device__ int   g_off[NTOT];
__device__ int   g_cursor[NTOT];     // after fill: end offset of each node
__device__ int   g_csr[ETOT];
__device__ int   g_bsumx[128];

// ---------------- helpers ----------------
__device__ __forceinline__ void red_add_v4(float* p, float4 v) {
    asm volatile("red.global.add.v4.f32 [%0], {%1,%2,%3,%4};"
                 :: "l"(p), "f"(v.x), "f"(v.y), "f"(v.z), "f"(v.w)
                 : "memory");
}

__device__ __forceinline__ void edge_sd(int e, const int* __restrict__ ec,
                                        const int* __restrict__ es, int& src, int& dst) {
    if (e < E_CHR) { src = ec[e]; dst = ec[E_CHR + e]; }
    else { int e2 = e - E_CHR; src = N_CHR + es[e2]; dst = N_CHR + es[E_SLV + e2]; }
}

// ---------------- CSR build ----------------
// also zeroes g_pool; requires g_deg == 0 at entry (maintained by gather64).
__global__ void count_deg_kernel(const int* __restrict__ ec, const int* __restrict__ es) {
    int e = blockIdx.x * blockDim.x + threadIdx.x;
    if (e < B * 384 / 4) ((float4*)g_pool)[e] = make_float4(0.f, 0.f, 0.f, 0.f);
    if (e >= ETOT) return;
    int src, dst; edge_sd(e, ec, es, src, dst);
    atomicAdd(&g_deg[dst], 1);
}

__global__ void scan1_kernel(int* __restrict__ bsum_raw) {
    __shared__ int s[SCAN_BLK];
    int tid = threadIdx.x;
    int i = blockIdx.x * SCAN_BLK + tid;
    int v = (i < NTOT) ? g_deg[i] : 0;
    s[tid] = v;
    __syncthreads();
    #pragma unroll
    for (int off = 1; off < SCAN_BLK; off <<= 1) {
        int t = (tid >= off) ? s[tid - off] : 0;
        __syncthreads();
        s[tid] += t;
        __syncthreads();
    }
    if (i < NTOT) g_incl[i] = s[tid];
    if (tid == SCAN_BLK - 1) bsum_raw[blockIdx.x] = s[tid];
}

__global__ void scan2_kernel(const int* __restrict__ bsum_raw) {
    __shared__ int s[128];
    int tid = threadIdx.x;
    int v = (tid < NB_SCAN) ? bsum_raw[tid] : 0;
    s[tid] = v;
    __syncthreads();
    #pragma unroll
    for (int off = 1; off < 128; off <<= 1) {
        int t = (tid >= off) ? s[tid - off] : 0;
        __syncthreads();
        s[tid] += t;
        __syncthreads();
    }
    g_bsumx[tid] = s[tid] - v;  // exclusive
}

__global__ void scan3_kernel() {
    int i = blockIdx.x * blockDim.x + threadIdx.x;
    if (i >= NTOT) return;
    int start = g_incl[i] - g_deg[i] + g_bsumx[i / SCAN_BLK];
    g_off[i] = start;
    g_cursor[i] = start;
}

__global__ void fill_csr_kernel(const int* __restrict__ ec, const int* __restrict__ es) {
    int e = blockIdx.x * blockDim.x + threadIdx.x;
    if (e >= ETOT) return;
    int src, dst; edge_sd(e, ec, es, src, dst);
    int pos = atomicAdd(&g_cursor[dst], 1);
    g_csr[pos] = src;
}

// ---------------- gathers ----------------
// first aggregation over raw features (64 wide); 2 nodes per warp.
// Also re-zeroes g_deg for the next run.
__global__ __launch_bounds__(256)
void gather64_kernel(const float* __restrict__ xchr, const float* __restrict__ xslv,
                     float* __restrict__ out) {
    int lane = threadIdx.x & 31;
    int sub = lane >> 4;
    int l = lane & 15;
    int hw = ((blockIdx.x * blockDim.x + threadIdx.x) >> 5) * 2 + sub;
    if (hw >= NTOT) return;
    int start = g_off[hw], deg = g_cursor[hw] - start;
    if (l == 0) g_deg[hw] = 0;
    float4 a = make_float4(0.f, 0.f, 0.f, 0.f);
    for (int kb = 0; kb < deg; kb += 16) {
        int idx = (kb + l < deg) ? g_csr[start + kb + l] : 0;
        int m = min(16, deg - kb);
        for (int k = 0; k < m; k++) {
            int s = __shfl_sync(0xffffffffu, idx, k, 16);
            const float4* sr = (s < N_CHR) ? (const float4*)(xchr + (size_t)s * 64)
                                           : (const float4*)(xslv + (size_t)(s - N_CHR) * 64);
            float4 v = sr[l];
            a.x += v.x; a.y += v.y; a.z += v.z; a.w += v.w;
        }
    }
    ((float4*)(out + (size_t)hw * 64))[l] = a;
}

// 384-wide aggregation over fp16 rows -> fp32 output. One warp per node.
__global__ __launch_bounds__(256)
void gather384h_kernel(const __half* __restrict__ in, float* __restrict__ out) {
    int lane = threadIdx.x & 31;
    int w = (blockIdx.x * blockDim.x + threadIdx.x) >> 5;
    if (w >= NTOT) return;
    int start = g_off[w], deg = g_cursor[w] - start;
    float a[8], b[8];
    #pragma unroll
    for (int i = 0; i < 8; i++) { a[i] = 0.f; b[i] = 0.f; }
    for (int kb = 0; kb < deg; kb += 32) {
        int idx = (kb + lane < deg) ? g_csr[start + kb + lane] : 0;
        int m = min(32, deg - kb);
        for (int k = 0; k < m; k++) {
            int s = __shfl_sync(0xffffffffu, idx, k);
            const uint4* sr = (const uint4*)(in + (size_t)s * 384);
            uint4 v = sr[lane];
            float2 f0 = __half22float2(*(__half2*)&v.x);
            float2 f1 = __half22float2(*(__half2*)&v.y);
            float2 f2 = __half22float2(*(__half2*)&v.z);
            float2 f3 = __half22float2(*(__half2*)&v.w);
            a[0] += f0.x; a[1] += f0.y; a[2] += f1.x; a[3] += f1.y;
            a[4] += f2.x; a[5] += f2.y; a[6] += f3.x; a[7] += f3.y;
            if (lane < 16) {
                uint4 v2 = sr[32 + lane];
                float2 g0 = __half22float2(*(__half2*)&v2.x);
                float2 g1 = __half22float2(*(__half2*)&v2.y);
                float2 g2 = __half22float2(*(__half2*)&v2.z);
                float2 g3 = __half22float2(*(__half2*)&v2.w);
                b[0] += g0.x; b[1] += g0.y; b[2] += g1.x; b[3] += g1.y;
                b[4] += g2.x; b[5] += g2.y; b[6] += g3.x; b[7] += g3.y;
            }
        }
    }
    float* orow = out + (size_t)w * 384;
    *(float4*)(orow + lane * 8)     = make_float4(a[0], a[1], a[2], a[3]);
    *(float4*)(orow + lane * 8 + 4) = make_float4(a[4], a[5], a[6], a[7]);
    if (lane < 16) {
        *(float4*)(orow + 256 + lane * 8)     = make_float4(b[0], b[1], b[2], b[3]);
        *(float4*)(orow + 256 + lane * 8 + 4) = make_float4(b[4], b[5], b[6], b[7]);
    }
}

// layer-2 aggregation (192-wide fp16 rows) fused with relu + global_add_pool
__global__ __launch_bounds__(256)
void gather192h_pool_kernel(const __half* __restrict__ in,
                            const int* __restrict__ bchr, const int* __restrict__ bslv) {
    int lane = threadIdx.x & 31;
    int w = (blockIdx.x * blockDim.x + threadIdx.x) >> 5;
    if (w >= NTOT) return;
    int start = g_off[w], deg = g_cursor[w] - start;
    bool act = lane < 24;
    float a[8];
    #pragma unroll
    for (int i = 0; i < 8; i++) a[i] = 0.f;
    for (int kb = 0; kb < deg; kb += 32) {
        int idx = (kb + lane < deg) ? g_csr[start + kb + lane] : 0;
        int m = min(32, deg - kb);
        for (int k = 0; k < m; k++) {
            int s = __shfl_sync(0xffffffffu, idx, k);
            if (act) {
                uint4 v = ((const uint4*)(in + (size_t)s * 192))[lane];
                float2 f0 = __half22float2(*(__half2*)&v.x);
                float2 f1 = __half22float2(*(__half2*)&v.y);
                float2 f2 = __half22float2(*(__half2*)&v.z);
                float2 f3 = __half22float2(*(__half2*)&v.w);
                a[0] += f0.x; a[1] += f0.y; a[2] += f1.x; a[3] += f1.y;
                a[4] += f2.x; a[5] += f2.y; a[6] += f3.x; a[7] += f3.y;
            }
        }
    }
    if (!act) return;
    #pragma unroll
    for (int i = 0; i < 8; i++) a[i] = fmaxf(a[i], 0.f);
    int b, colbase;
    if (w < N_CHR) { b = bchr[w]; colbase = 0; }
    else           { b = bslv[w - N_CHR]; colbase = 192; }
    float* prow = g_pool + (size_t)b * 384 + colbase;
    red_add_v4(prow + lane * 8,     make_float4(a[0], a[1], a[2], a[3]));
    red_add_v4(prow + lane * 8 + 4, make_float4(a[4], a[5], a[6], a[7]));
}

// ---------------- register-tiled GEMM (R3 version + optional fp16 output) --
// out[n, e*out_eoff + j] = (relu?)( in[n, e*in_eoff + 0:K] @ W[e] )
// 256 threads; micro-tile 8 rows x MC cols per thread.
template<int K, int MOUT, int MC, bool RELU_IN, bool RELU_OUT, bool OUT_HALF>
__global__ __launch_bounds__(256, 1)
void gemm_kernel(const float* __restrict__ in, void* __restrict__ outv,
                 const float* __restrict__ Wc, const float* __restrict__ Ws,
                 int in_stride, int in_eoff, int out_stride, int out_eoff) {
    constexpr int CG = MOUT / MC;       // col groups
    constexpr int RG = 256 / CG;        // row groups
    constexpr int TR = RG * 8;          // rows per tile
    constexpr int TRP = TR + 4;         // padded
    extern __shared__ float sm[];
    float* sW   = sm;                   // [K][MOUT]
    float* sInT = sm + K * MOUT;        // [K][TRP] transposed input tile

    const int e = blockIdx.y;
    const int branch = blockIdx.z;
    const int tid = threadIdx.x;
    const int cgrp = tid % CG;
    const int rgrp = tid / CG;
    const int j0 = cgrp * MC;

    const int base  = branch ? N_CHR : 0;
    const int nrows = branch ? N_SLV : N_CHR;
    const int ntiles = (nrows + TR - 1) / TR;
    const float* W = (branch ? Ws : Wc) + (size_t)e * K * MOUT;

    for (int i = tid; i < K * MOUT / 4; i += 256)
        ((float4*)sW)[i] = ((const float4*)W)[i];
    __syncthreads();

    for (int t = blockIdx.x; t < ntiles; t += gridDim.x) {
        int row0 = base + t * TR;
        int rcnt = min(TR, base + nrows - row0);
        constexpr int C4 = TR * (K / 4);
        for (int i = tid; i < C4; i += 256) {
            int r = i / (K / 4), kc = i % (K / 4);
            float4 v = make_float4(0.f, 0.f, 0.f, 0.f);
            if (r < rcnt) {
                v = *(const float4*)(in + (size_t)(row0 + r) * in_stride + (size_t)e * in_eoff + kc * 4);
                if (RELU_IN) {
                    v.x = fmaxf(v.x, 0.f); v.y = fmaxf(v.y, 0.f);
                    v.z = fmaxf(v.z, 0.f); v.w = fmaxf(v.w, 0.f);
                }
            }
            int kk = kc * 4;
            sInT[(kk + 0) * TRP + r] = v.x;
            sInT[(kk + 1) * TRP + r] = v.y;
            sInT[(kk + 2) * TRP + r] = v.z;
            sInT[(kk + 3) * TRP + r] = v.w;
        }
        __syncthreads();

        float acc[8][MC];
        #pragma unroll
        for (int r = 0; r < 8; r++)
            #pragma unroll
            for (int c = 0; c < MC; c++) acc[r][c] = 0.f;

        #pragma unroll 4
        for (int k = 0; k < K; k++) {
            float4 A0 = *(const float4*)(sInT + k * TRP + rgrp * 8);
            float4 A1 = *(const float4*)(sInT + k * TRP + rgrp * 8 + 4);
            float a[8] = {A0.x, A0.y, A0.z, A0.w, A1.x, A1.y, A1.z, A1.w};
            float wv[MC];
            float4 W0 = *(const float4*)(sW + k * MOUT + j0);
            wv[0] = W0.x; wv[1] = W0.y; wv[2] = W0.z; wv[3] = W0.w;
            if (MC == 8) {
                float4 W1 = *(const float4*)(sW + k * MOUT + j0 + 4);
                wv[4] = W1.x; wv[5] = W1.y; wv[6] = W1.z; wv[7] = W1.w;
            }
            #pragma unroll
            for (int r = 0; r < 8; r++)
                #pragma unroll
                for (int c = 0; c < MC; c++)
                    acc[r][c] = fmaf(a[r], wv[c], acc[r][c]);
        }

        #pragma unroll
        for (int r = 0; r < 8; r++) {
            int rr = rgrp * 8 + r;
            if (rr < rcnt) {
                if (!OUT_HALF) {
                    float* op = (float*)outv + (size_t)(row0 + rr) * out_stride + (size_t)e * out_eoff + j0;
                    #pragma unroll
                    for (int c0 = 0; c0 < MC; c0 += 4) {
                        float4 v;
                        v.x = acc[r][c0 + 0]; v.y = acc[r][c0 + 1];
                        v.z = acc[r][c0 + 2]; v.w = acc[r][c0 + 3];
                        if (RELU_OUT) {
                            v.x = fmaxf(v.x, 0.f); v.y = fmaxf(v.y, 0.f);
                            v.z = fmaxf(v.z, 0.f); v.w = fmaxf(v.w, 0.f);
                        }
                        *(float4*)(op + c0) = v;
                    }
                } else {
                    __half2 h2[MC / 2];
                    #pragma unroll
                    for (int c = 0; c < MC; c += 2) {
                        float x = acc[r][c], y = acc[r][c + 1];
                        if (RELU_OUT) { x = fmaxf(x, 0.f); y = fmaxf(y, 0.f); }
                        h2[c / 2] = __floats2half2_rn(x, y);
                    }
                    __half* op = (__half*)outv + (size_t)(row0 + rr) * out_stride + (size_t)e * out_eoff + j0;
                    if (MC == 8) {
                        uint4 u;
                        u.x = *(unsigned*)&h2[0]; u.y = *(unsigned*)&h2[1];
                        u.z = *(unsigned*)&h2[2]; u.w = *(unsigned*)&h2[3];
                        *(uint4*)op = u;
                    } else {
                        uint2 u;
                        u.x = *(unsigned*)&h2[0]; u.y = *(unsigned*)&h2[1];
                        *(uint2*)op = u;
                    }
                }
            }
        }
        __syncthreads();
    }
}

// ---------------- head: projection heads + concat + fc1 + fc2 -------------
__global__ __launch_bounds__(128)
void head_kernel(const float* __restrict__ cfcW, const float* __restrict__ cfcb,
                 const float* __restrict__ sfcW, const float* __restrict__ sfcb,
                 const float* __restrict__ fc1W, const float* __restrict__ fc1b,
                 const float* __restrict__ fc2W, const float* __restrict__ fc2b,
                 float* __restrict__ out) {
    __shared__ float sPool[384];
    __shared__ float sHg[768];
    __shared__ float sRed[128];
    const int b = blockIdx.x;
    const int tid = threadIdx.x;

    for (int i = tid; i < 384; i += 128) sPool[i] = g_pool[(size_t)b * 384 + i];
    __syncthreads();

    #pragma unroll
    for (int p = 0; p < 6; p++) {
        const bool slv = (p >= 3);
        const int e = slv ? (p - 3) : p;
        const float* W = slv ? sfcW : cfcW;
        const float* bias = slv ? sfcb : cfcb;
        const float* rep = sPool + (slv ? 192 : 0) + e * HALF;
        float acc = bias[e * DIM + tid];
        #pragma unroll 8
        for (int k = 0; k < HALF; k++)
            acc = fmaf(rep[k], W[(size_t)e * HALF * DIM + k * DIM + tid], acc);
        sHg[p * DIM + tid] = fmaxf(acc, 0.f);
    }
    __syncthreads();

    float acc = fc1b[tid];
    #pragma unroll 8
    for (int h = 0; h < 768; h++)
        acc = fmaf(sHg[h], fc1W[(size_t)h * DIM + tid], acc);
    float o1 = fmaxf(acc, 0.f);

    sRed[tid] = o1 * fc2W[tid];
    __syncthreads();
    if (tid < 64) sRed[tid] += sRed[tid + 64];
    __syncthreads();
    if (tid < 32) {
        float x = sRed[tid] + sRed[tid + 32];
        #pragma unroll
        for (int o = 16; o; o >>= 1) x += __shfl_down_sync(0xffffffffu, x, o);
        if (tid == 0) out[b] = x + fc2b[0];
    }
}

// ---------------- launch ----------------
extern "C" void kernel_launch(void* const* d_in, const int* in_sizes, int n_in,
                              void* d_out, int out_size) {
    const float* chr_x  = (const float*)d_in[0];
    const float* slv_x  = (const float*)d_in[1];
    const int*   chr_ei = (const int*)d_in[2];
    const int*   slv_ei = (const int*)d_in[3];
    const int*   chr_b  = (const int*)d_in[4];
    const int*   slv_b  = (const int*)d_in[5];
    const float* chr_W0 = (const float*)d_in[6];
    const float* chr_W1 = (const float*)d_in[7];
    const float* chr_W2 = (const float*)d_in[8];
    const float* slv_W0 = (const float*)d_in[9];
    const float* slv_W1 = (const float*)d_in[10];
    const float* slv_W2 = (const float*)d_in[11];
    const float* cfcW   = (const float*)d_in[12];
    const float* cfcb   = (const float*)d_in[13];
    const float* sfcW   = (const float*)d_in[14];
    const float* sfcb   = (const float*)d_in[15];
    const float* fc1W   = (const float*)d_in[16];
    const float* fc1b   = (const float*)d_in[17];
    const float* fc2W   = (const float*)d_in[18];
    const float* fc2b   = (const float*)d_in[19];
    float* out = (float*)d_out;

    float *aggx, *buf1, *buf2;
    int* csr;
    cudaGetSymbolAddress((void**)&aggx, g_aggx);
    cudaGetSymbolAddress((void**)&buf1, g_buf1);
    cudaGetSymbolAddress((void**)&buf2, g_buf2);
    cudaGetSymbolAddress((void**)&csr, g_csr);

    // smem: sW (K*MOUT) + sInT (K*TRP), floats
    constexpr int SM0 = (64  * 128 + 64  * 132) * 4;   // 66560
    constexpr int SM1 = (128 * 128 + 128 * 132) * 4;   // 133120
    constexpr int SM2 = (128 * 64  + 128 * 132) * 4;   // 100352
    cudaFuncSetAttribute((const void*)gemm_kernel<64, 128, 8, false, true, false>,
                         cudaFuncAttributeMaxDynamicSharedMemorySize, SM0);
    cudaFuncSetAttribute((const void*)gemm_kernel<128, 128, 8, false, false, true>,
                         cudaFuncAttributeMaxDynamicSharedMemorySize, SM1);
    cudaFuncSetAttribute((const void*)gemm_kernel<128, 64, 4, true, false, true>,
                         cudaFuncAttributeMaxDynamicSharedMemorySize, SM2);

    dim3 ggrid(148, ENS, 2);

    // ---- CSR build (g_deg zero at entry; re-zeroed inside gather64) ----
    count_deg_kernel<<<(ETOT + 255) / 256, 256>>>(chr_ei, slv_ei);   // + pool zero
    scan1_kernel<<<NB_SCAN, SCAN_BLK>>>(csr + ETOT - 128);  // raw block sums in csr tail
    scan2_kernel<<<1, 128>>>(csr + ETOT - 128);
    scan3_kernel<<<(NTOT + 255) / 256, 256>>>();
    fill_csr_kernel<<<(ETOT + 255) / 256, 256>>>(chr_ei, slv_ei);

    // ---- forward pass ----
    // 1) aggx = A x   (shared across ensembles, 64 wide)
    gather64_kernel<<<(NTOT / 2 + 7) / 8, 256>>>(chr_x, slv_x, aggx);
    // 2) h0 = relu(aggx @ W0) -> buf1 fp32 [N, 3*128]
    gemm_kernel<64, 128, 8, false, true, false><<<ggrid, 256, SM0>>>(
        aggx, buf1, chr_W0, slv_W0, FEAT, 0, ENS * DIM, DIM);
    // 3) t1 = h0 @ W1 -> buf2 as fp16 [N, 3*128]
    gemm_kernel<128, 128, 8, false, false, true><<<ggrid, 256, SM1>>>(
        buf1, buf2, chr_W1, slv_W1, ENS * DIM, DIM, ENS * DIM, DIM);
    // 4) agg1 = A t1 -> buf1 fp32
    gather384h_kernel<<<NTOT / 8, 256>>>((const __half*)buf2, buf1);
    // 5) t2 = relu(agg1) @ W2 -> buf2 as fp16 [N, 3*64]
    gemm_kernel<128, 64, 4, true, false, true><<<ggrid, 256, SM2>>>(
        buf1, buf2, chr_W2, slv_W2, ENS * DIM, DIM, ENS * HALF, HALF);
    // 6) pool[batch] += relu(A t2)   (fused aggregation + relu + pool)
    gather192h_pool_kernel<<<NTOT / 8, 256>>>((const __half*)buf2, chr_b, slv_b);
    // 7) head
    head_kernel<<<B, 128>>>(cfcW, cfcb, sfcW, sfcb, fc1W, fc1b, fc2W, fc2b, out);
}

// round 6
// speedup vs baseline: 3.1552x; 1.6737x over previous
#include <cuda_runtime.h>
#include <cuda_bf16.h>
#include <cuda_fp16.h>

// ---------------- problem constants ----------------
constexpr int N_CHR = 50000, E_CHR = 500000;
constexpr int N_SLV = 30000, E_SLV = 300000;
constexpr int NTOT = N_CHR + N_SLV;      // 80000
constexpr int ETOT = E_CHR + E_SLV;      // 800000
constexpr int B    = 256;
constexpr int FEAT = 64;
constexpr int DIM  = 128;
constexpr int HALF = 64;
constexpr int ENS  = 3;
constexpr int SCAN_BLK = 1024;
constexpr int NB_SCAN = (NTOT + SCAN_BLK - 1) / SCAN_BLK;  // 79

// ---------------- scratch (device globals; no allocations allowed) --------
__device__ __align__(128) __half g_aggx[(size_t)NTOT * FEAT];
__device__ __align__(128) __half g_buf1[(size_t)NTOT * ENS * DIM];   // h0 / agg1
__device__ __align__(128) __half g_buf2[(size_t)NTOT * ENS * DIM];   // t1 / t2
__device__ float g_pool[(size_t)B * 2 * ENS * HALF];
__device__ int   g_deg[NTOT];        // ZERO at entry of every run (static init + re-zero in gather64)
__device__ int   g_incl[NTOT];
__device__ int   g_off[NTOT];
__device__ int   g_cursor[NTOT];     // after fill: end offset of each node
__device__ int   g_csr[ETOT];
__device__ int   g_bsumx[128];

// ---------------- helpers ----------------
__device__ __forceinline__ void red_add_v4(float* p, float4 v) {
    asm volatile("red.global.add.v4.f32 [%0], {%1,%2,%3,%4};"
                 :: "l"(p), "f"(v.x), "f"(v.y), "f"(v.z), "f"(v.w)
                 : "memory");
}

__device__ __forceinline__ void edge_sd(int e, const int* __restrict__ ec,
                                        const int* __restrict__ es, int& src, int& dst) {
    if (e < E_CHR) { src = ec[e]; dst = ec[E_CHR + e]; }
    else { int e2 = e - E_CHR; src = N_CHR + es[e2]; dst = N_CHR + es[E_SLV + e2]; }
}

__device__ __forceinline__ void ldsm_x4(unsigned* r, unsigned addr) {
    asm volatile("ldmatrix.sync.aligned.m8n8.x4.shared.b16 {%0,%1,%2,%3}, [%4];"
                 : "=r"(r[0]), "=r"(r[1]), "=r"(r[2]), "=r"(r[3]) : "r"(addr));
}
__device__ __forceinline__ void ldsm_x2t(unsigned* r, unsigned addr) {
    asm volatile("ldmatrix.sync.aligned.m8n8.x2.trans.shared.b16 {%0,%1}, [%2];"
                 : "=r"(r[0]), "=r"(r[1]) : "r"(addr));
}
__device__ __forceinline__ void mma16816(float* d, const unsigned* a, const unsigned* b) {
    asm volatile("mma.sync.aligned.m16n8k16.row.col.f32.f16.f16.f32 "
                 "{%0,%1,%2,%3}, {%4,%5,%6,%7}, {%8,%9}, {%0,%1,%2,%3};"
                 : "+f"(d[0]), "+f"(d[1]), "+f"(d[2]), "+f"(d[3])
                 : "r"(a[0]), "r"(a[1]), "r"(a[2]), "r"(a[3]), "r"(b[0]), "r"(b[1]));
}

// ---------------- CSR build ----------------
// also zeroes g_pool; requires g_deg == 0 at entry (maintained by gather64).
__global__ void count_deg_kernel(const int* __restrict__ ec, const int* __restrict__ es) {
    int e = blockIdx.x * blockDim.x + threadIdx.x;
    if (e < B * 384 / 4) ((float4*)g_pool)[e] = make_float4(0.f, 0.f, 0.f, 0.f);
    if (e >= ETOT) return;
    int src, dst; edge_sd(e, ec, es, src, dst);
    atomicAdd(&g_deg[dst], 1);
}

__global__ void scan1_kernel(int* __restrict__ bsum_raw) {
    __shared__ int s[SCAN_BLK];
    int tid = threadIdx.x;
    int i = blockIdx.x * SCAN_BLK + tid;
    int v = (i < NTOT) ? g_deg[i] : 0;
    s[tid] = v;
    __syncthreads();
    #pragma unroll
    for (int off = 1; off < SCAN_BLK; off <<= 1) {
        int t = (tid >= off) ? s[tid - off] : 0;
        __syncthreads();
        s[tid] += t;
        __syncthreads();
    }
    if (i < NTOT) g_incl[i] = s[tid];
    if (tid == SCAN_BLK - 1) bsum_raw[blockIdx.x] = s[tid];
}

__global__ void scan2_kernel(const int* __restrict__ bsum_raw) {
    __shared__ int s[128];
    int tid = threadIdx.x;
    int v = (tid < NB_SCAN) ? bsum_raw[tid] : 0;
    s[tid] = v;
    __syncthreads();
    #pragma unroll
    for (int off = 1; off < 128; off <<= 1) {
        int t = (tid >= off) ? s[tid - off] : 0;
        __syncthreads();
        s[tid] += t;
        __syncthreads();
    }
    g_bsumx[tid] = s[tid] - v;  // exclusive
}

__global__ void scan3_kernel() {
    int i = blockIdx.x * blockDim.x + threadIdx.x;
    if (i >= NTOT) return;
    int start = g_incl[i] - g_deg[i] + g_bsumx[i / SCAN_BLK];
    g_off[i] = start;
    g_cursor[i] = start;
}

__global__ void fill_csr_kernel(const int* __restrict__ ec, const int* __restrict__ es) {
    int e = blockIdx.x * blockDim.x + threadIdx.x;
    if (e >= ETOT) return;
    int src, dst; edge_sd(e, ec, es, src, dst);
    int pos = atomicAdd(&g_cursor[dst], 1);
    g_csr[pos] = src;
}

// ---------------- gathers ----------------
// first aggregation over raw fp32 features -> fp16 output; 2 nodes per warp.
// Also re-zeroes g_deg for the next run.
__global__ __launch_bounds__(256)
void gather64_kernel(const float* __restrict__ xchr, const float* __restrict__ xslv,
                     __half* __restrict__ out) {
    int lane = threadIdx.x & 31;
    int sub = lane >> 4;
    int l = lane & 15;
    int hw = ((blockIdx.x * blockDim.x + threadIdx.x) >> 5) * 2 + sub;
    if (hw >= NTOT) return;
    int start = g_off[hw], deg = g_cursor[hw] - start;
    if (l == 0) g_deg[hw] = 0;
    float4 a = make_float4(0.f, 0.f, 0.f, 0.f);
    for (int kb = 0; kb < deg; kb += 16) {
        int idx = (kb + l < deg) ? g_csr[start + kb + l] : 0;
        int m = min(16, deg - kb);
        for (int k = 0; k < m; k++) {
            int s = __shfl_sync(0xffffffffu, idx, k, 16);
            const float4* sr = (s < N_CHR) ? (const float4*)(xchr + (size_t)s * 64)
                                           : (const float4*)(xslv + (size_t)(s - N_CHR) * 64);
            float4 v = sr[l];
            a.x += v.x; a.y += v.y; a.z += v.z; a.w += v.w;
        }
    }
    __half2 h0 = __floats2half2_rn(a.x, a.y);
    __half2 h1 = __floats2half2_rn(a.z, a.w);
    uint2 u; u.x = *(unsigned*)&h0; u.y = *(unsigned*)&h1;
    *(uint2*)(out + (size_t)hw * 64 + l * 4) = u;
}

// 384-wide aggregation over fp16 rows -> relu -> fp16 output. One warp per node.
__global__ __launch_bounds__(256)
void gather384h_kernel(const __half* __restrict__ in, __half* __restrict__ out) {
    int lane = threadIdx.x & 31;
    int w = (blockIdx.x * blockDim.x + threadIdx.x) >> 5;
    if (w >= NTOT) return;
    int start = g_off[w], deg = g_cursor[w] - start;
    float a[8], b[8];
    #pragma unroll
    for (int i = 0; i < 8; i++) { a[i] = 0.f; b[i] = 0.f; }
    for (int kb = 0; kb < deg; kb += 32) {
        int idx = (kb + lane < deg) ? g_csr[start + kb + lane] : 0;
        int m = min(32, deg - kb);
        for (int k = 0; k < m; k++) {
            int s = __shfl_sync(0xffffffffu, idx, k);
            const uint4* sr = (const uint4*)(in + (size_t)s * 384);
            uint4 v = sr[lane];
            float2 f0 = __half22float2(*(__half2*)&v.x);
            float2 f1 = __half22float2(*(__half2*)&v.y);
            float2 f2 = __half22float2(*(__half2*)&v.z);
            float2 f3 = __half22float2(*(__half2*)&v.w);
            a[0] += f0.x; a[1] += f0.y; a[2] += f1.x; a[3] += f1.y;
            a[4] += f2.x; a[5] += f2.y; a[6] += f3.x; a[7] += f3.y;
            if (lane < 16) {
                uint4 v2 = sr[32 + lane];
                float2 g0 = __half22float2(*(__half2*)&v2.x);
                float2 g1 = __half22float2(*(__half2*)&v2.y);
                float2 g2 = __half22float2(*(__half2*)&v2.z);
                float2 g3 = __half22float2(*(__half2*)&v2.w);
                b[0] += g0.x; b[1] += g0.y; b[2] += g1.x; b[3] += g1.y;
                b[4] += g2.x; b[5] += g2.y; b[6] += g3.x; b[7] += g3.y;
            }
        }
    }
    // relu + fp16 pack (agg1 is consumed only through relu)
    uint4 o;
    __half2 h;
    h = __floats2half2_rn(fmaxf(a[0],0.f), fmaxf(a[1],0.f)); o.x = *(unsigned*)&h;
    h = __floats2half2_rn(fmaxf(a[2],0.f), fmaxf(a[3],0.f)); o.y = *(unsigned*)&h;
    h = __floats2half2_rn(fmaxf(a[4],0.f), fmaxf(a[5],0.f)); o.z = *(unsigned*)&h;
    h = __floats2half2_rn(fmaxf(a[6],0.f), fmaxf(a[7],0.f)); o.w = *(unsigned*)&h;
    uint4* orow = (uint4*)(out + (size_t)w * 384);
    orow[lane] = o;
    if (lane < 16) {
        uint4 o2;
        h = __floats2half2_rn(fmaxf(b[0],0.f), fmaxf(b[1],0.f)); o2.x = *(unsigned*)&h;
        h = __floats2half2_rn(fmaxf(b[2],0.f), fmaxf(b[3],0.f)); o2.y = *(unsigned*)&h;
        h = __floats2half2_rn(fmaxf(b[4],0.f), fmaxf(b[5],0.f)); o2.z = *(unsigned*)&h;
        h = __floats2half2_rn(fmaxf(b[6],0.f), fmaxf(b[7],0.f)); o2.w = *(unsigned*)&h;
        orow[32 + lane] = o2;
    }
}

// layer-2 aggregation (192-wide fp16 rows) fused with relu + global_add_pool
__global__ __launch_bounds__(256)
void gather192h_pool_kernel(const __half* __restrict__ in,
                            const int* __restrict__ bchr, const int* __restrict__ bslv) {
    int lane = threadIdx.x & 31;
    int w = (blockIdx.x * blockDim.x + threadIdx.x) >> 5;
    if (w >= NTOT) return;
    int start = g_off[w], deg = g_cursor[w] - start;
    bool act = lane < 24;
    float a[8];
    #pragma unroll
    for (int i = 0; i < 8; i++) a[i] = 0.f;
    for (int kb = 0; kb < deg; kb += 32) {
        int idx = (kb + lane < deg) ? g_csr[start + kb + lane] : 0;
        int m = min(32, deg - kb);
        for (int k = 0; k < m; k++) {
            int s = __shfl_sync(0xffffffffu, idx, k);
            if (act) {
                uint4 v = ((const uint4*)(in + (size_t)s * 192))[lane];
                float2 f0 = __half22float2(*(__half2*)&v.x);
                float2 f1 = __half22float2(*(__half2*)&v.y);
                float2 f2 = __half22float2(*(__half2*)&v.z);
                float2 f3 = __half22float2(*(__half2*)&v.w);
                a[0] += f0.x; a[1] += f0.y; a[2] += f1.x; a[3] += f1.y;
                a[4] += f2.x; a[5] += f2.y; a[6] += f3.x; a[7] += f3.y;
            }
        }
    }
    if (!act) return;
    #pragma unroll
    for (int i = 0; i < 8; i++) a[i] = fmaxf(a[i], 0.f);
    int b, colbase;
    if (w < N_CHR) { b = bchr[w]; colbase = 0; }
    else           { b = bslv[w - N_CHR]; colbase = 192; }
    float* prow = g_pool + (size_t)b * 384 + colbase;
    red_add_v4(prow + lane * 8,     make_float4(a[0], a[1], a[2], a[3]));
    red_add_v4(prow + lane * 8 + 4, make_float4(a[4], a[5], a[6], a[7]));
}

// ---------------- fp16 tensor-core GEMM -----------------------------------
// out[n, e*out_eoff + j] = (relu?)( in[n, e*in_eoff + 0:K] @ W[e] )
// All strides/offsets in __half elements. 256 threads = 8 warps; block row
// tile 128. MOUT=128: 4 rowgrps x 2 colgrps, warp tile 32x64.
// MOUT=64: 8 rowgrps x 1 colgrp, warp tile 16x64.
template<int K, int MOUT, bool RELU_OUT>
__global__ __launch_bounds__(256, 1)
void hgemm_kernel(const __half* __restrict__ in, __half* __restrict__ out,
                  const float* __restrict__ Wc, const float* __restrict__ Ws,
                  int in_stride, int in_eoff, int out_stride, int out_eoff) {
    constexpr int TR = 128;
    constexpr int CGS = MOUT / 64;          // col groups (1 or 2)
    constexpr int RGS = 8 / CGS;            // row groups
    constexpr int WM = TR / RGS;            // warp rows (32 or 16)
    constexpr int MT = WM / 16;             // m-tiles per warp (2 or 1)
    constexpr int LDA = K + 8;
    constexpr int LDB = MOUT + 8;
    constexpr int KS = K / 16;

    extern __shared__ __half hsm[];
    __half* sA = hsm;                       // [TR][LDA]
    __half* sB = hsm + TR * LDA;            // [K][LDB]

    const int e = blockIdx.y;
    const int branch = blockIdx.z;
    const int tid = threadIdx.x;
    const int wid = tid >> 5;
    const int lane = tid & 31;
    const int rowgrp = wid / CGS;
    const int colgrp = wid % CGS;

    const int base  = branch ? N_CHR : 0;
    const int nrows = branch ? N_SLV : N_CHR;
    const int ntiles = (nrows + TR - 1) / TR;
    const float* W = (branch ? Ws : Wc) + (size_t)e * K * MOUT;

    // weights fp32 -> fp16 smem [k][n]
    for (int idx = tid; idx < K * MOUT / 4; idx += 256) {
        int k = idx / (MOUT / 4), c = idx % (MOUT / 4);
        float4 w = ((const float4*)W)[idx];
        __half2 h0 = __floats2half2_rn(w.x, w.y);
        __half2 h1 = __floats2half2_rn(w.z, w.w);
        uint2 u; u.x = *(unsigned*)&h0; u.y = *(unsigned*)&h1;
        *(uint2*)(sB + k * LDB + c * 4) = u;
    }
    __syncthreads();

    unsigned sa_base = (unsigned)__cvta_generic_to_shared(sA);
    unsigned sb_base = (unsigned)__cvta_generic_to_shared(sB);

    for (int t = blockIdx.x; t < ntiles; t += gridDim.x) {
        int row0 = base + t * TR;
        int rcnt = min(TR, base + nrows - row0);

        // load A tile (fp16 rows, uint4 = 8 halves)
        constexpr int C8 = TR * (K / 8);
        for (int i = tid; i < C8; i += 256) {
            int r = i / (K / 8), c = i % (K / 8);
            uint4 v = make_uint4(0u, 0u, 0u, 0u);
            if (r < rcnt)
                v = *(const uint4*)(in + (size_t)(row0 + r) * in_stride + (size_t)e * in_eoff + c * 8);
            *(uint4*)(sA + r * LDA + c * 8) = v;
        }
        __syncthreads();

        float acc[MT][8][4];
        #pragma unroll
        for (int mt = 0; mt < MT; mt++)
            #pragma unroll
            for (int nt = 0; nt < 8; nt++)
                #pragma unroll
                for (int q = 0; q < 4; q++) acc[mt][nt][q] = 0.f;

        #pragma unroll
        for (int ks = 0; ks < KS; ks++) {
            unsigned a[MT][4];
            #pragma unroll
            for (int mt = 0; mt < MT; mt++) {
                int r = rowgrp * WM + mt * 16 + (lane & 15);
                int c = ks * 16 + (lane >> 4) * 8;
                ldsm_x4(a[mt], sa_base + (r * LDA + c) * 2);
            }
            #pragma unroll
            for (int nt = 0; nt < 8; nt++) {
                unsigned b[2];
                int rk = ks * 16 + (lane & 15);
                int cn = colgrp * 64 + nt * 8;
                ldsm_x2t(b, sb_base + (rk * LDB + cn) * 2);
                #pragma unroll
                for (int mt = 0; mt < MT; mt++)
                    mma16816(acc[mt][nt], a[mt], b);
            }
        }

        // epilogue: fp16 (+relu) stores
        int lrow = lane >> 2, lcol = (lane & 3) * 2;
        #pragma unroll
        for (int mt = 0; mt < MT; mt++) {
            #pragma unroll
            for (int nt = 0; nt < 8; nt++) {
                int col = colgrp * 64 + nt * 8 + lcol;
                int r1 = rowgrp * WM + mt * 16 + lrow;
                float x0 = acc[mt][nt][0], x1 = acc[mt][nt][1];
                float x2 = acc[mt][nt][2], x3 = acc[mt][nt][3];
                if (RELU_OUT) {
                    x0 = fmaxf(x0, 0.f); x1 = fmaxf(x1, 0.f);
                    x2 = fmaxf(x2, 0.f); x3 = fmaxf(x3, 0.f);
                }
                if (r1 < rcnt) {
                    __half2 h = __floats2half2_rn(x0, x1);
                    *(__half2*)(out + (size_t)(row0 + r1) * out_stride + (size_t)e * out_eoff + col) = h;
                }
                if (r1 + 8 < rcnt) {
                    __half2 h = __floats2half2_rn(x2, x3);
                    *(__half2*)(out + (size_t)(row0 + r1 + 8) * out_stride + (size_t)e * out_eoff + col) = h;
                }
            }
        }
        __syncthreads();
    }
}

// ---------------- head: projection heads + concat + fc1 + fc2 -------------
__global__ __launch_bounds__(128)
void head_kernel(const float* __restrict__ cfcW, const float* __restrict__ cfcb,
                 const float* __restrict__ sfcW, const float* __restrict__ sfcb,
                 const float* __restrict__ fc1W, const float* __restrict__ fc1b,
                 const float* __restrict__ fc2W, const float* __restrict__ fc2b,
                 float* __restrict__ out) {
    __shared__ float sPool[384];
    __shared__ float sHg[768];
    __shared__ float sRed[128];
    const int b = blockIdx.x;
    const int tid = threadIdx.x;

    for (int i = tid; i < 384; i += 128) sPool[i] = g_pool[(size_t)b * 384 + i];
    __syncthreads();

    #pragma unroll
    for (int p = 0; p < 6; p++) {
        const bool slv = (p >= 3);
        const int e = slv ? (p - 3) : p;
        const float* W = slv ? sfcW : cfcW;
        const float* bias = slv ? sfcb : cfcb;
        const float* rep = sPool + (slv ? 192 : 0) + e * HALF;
        float acc = bias[e * DIM + tid];
        #pragma unroll 8
        for (int k = 0; k < HALF; k++)
            acc = fmaf(rep[k], W[(size_t)e * HALF * DIM + k * DIM + tid], acc);
        sHg[p * DIM + tid] = fmaxf(acc, 0.f);
    }
    __syncthreads();

    float acc = fc1b[tid];
    #pragma unroll 8
    for (int h = 0; h < 768; h++)
        acc = fmaf(sHg[h], fc1W[(size_t)h * DIM + tid], acc);
    float o1 = fmaxf(acc, 0.f);

    sRed[tid] = o1 * fc2W[tid];
    __syncthreads();
    if (tid < 64) sRed[tid] += sRed[tid + 64];
    __syncthreads();
    if (tid < 32) {
        float x = sRed[tid] + sRed[tid + 32];
        #pragma unroll
        for (int o = 16; o; o >>= 1) x += __shfl_down_sync(0xffffffffu, x, o);
        if (tid == 0) out[b] = x + fc2b[0];
    }
}

// ---------------- launch ----------------
extern "C" void kernel_launch(void* const* d_in, const int* in_sizes, int n_in,
                              void* d_out, int out_size) {
    const float* chr_x  = (const float*)d_in[0];
    const float* slv_x  = (const float*)d_in[1];
    const int*   chr_ei = (const int*)d_in[2];
    const int*   slv_ei = (const int*)d_in[3];
    const int*   chr_b  = (const int*)d_in[4];
    const int*   slv_b  = (const int*)d_in[5];
    const float* chr_W0 = (const float*)d_in[6];
    const float* chr_W1 = (const float*)d_in[7];
    const float* chr_W2 = (const float*)d_in[8];
    const float* slv_W0 = (const float*)d_in[9];
    const float* slv_W1 = (const float*)d_in[10];
    const float* slv_W2 = (const float*)d_in[11];
    const float* cfcW   = (const float*)d_in[12];
    const float* cfcb   = (const float*)d_in[13];
    const float* sfcW   = (const float*)d_in[14];
    const float* sfcb   = (const float*)d_in[15];
    const float* fc1W   = (const float*)d_in[16];
    const float* fc1b   = (const float*)d_in[17];
    const float* fc2W   = (const float*)d_in[18];
    const float* fc2b   = (const float*)d_in[19];
    float* out = (float*)d_out;

    __half *aggx, *buf1, *buf2;
    int* csr;
    cudaGetSymbolAddress((void**)&aggx, g_aggx);
    cudaGetSymbolAddress((void**)&buf1, g_buf1);
    cudaGetSymbolAddress((void**)&buf2, g_buf2);
    cudaGetSymbolAddress((void**)&csr, g_csr);

    // dynamic smem: (TR*LDA + K*LDB) halves
    constexpr int SM0 = (128 * 72  + 64  * 136) * 2;  // 35840
    constexpr int SM1 = (128 * 136 + 128 * 136) * 2;  // 69632
    constexpr int SM2 = (128 * 136 + 128 * 72)  * 2;  // 53248
    cudaFuncSetAttribute((const void*)hgemm_kernel<64, 128, true>,
                         cudaFuncAttributeMaxDynamicSharedMemorySize, SM0);
    cudaFuncSetAttribute((const void*)hgemm_kernel<128, 128, false>,
                         cudaFuncAttributeMaxDynamicSharedMemorySize, SM1);
    cudaFuncSetAttribute((const void*)hgemm_kernel<128, 64, false>,
                         cudaFuncAttributeMaxDynamicSharedMemorySize, SM2);

    dim3 ggrid(391, ENS, 2);  // 391 = ceil(50000/128)

    // ---- CSR build (g_deg zero at entry; re-zeroed inside gather64) ----
    count_deg_kernel<<<(ETOT + 255) / 256, 256>>>(chr_ei, slv_ei);   // + pool zero
    scan1_kernel<<<NB_SCAN, SCAN_BLK>>>(csr + ETOT - 128);  // raw block sums in csr tail
    scan2_kernel<<<1, 128>>>(csr + ETOT - 128);
    scan3_kernel<<<(NTOT + 255) / 256, 256>>>();
    fill_csr_kernel<<<(ETOT + 255) / 256, 256>>>(chr_ei, slv_ei);

    // ---- forward pass ----
    // 1) aggx = A x -> fp16 [N,64]
    gather64_kernel<<<(NTOT / 2 + 7) / 8, 256>>>(chr_x, slv_x, aggx);
    // 2) h0 = relu(aggx @ W0) -> buf1 fp16 [N, 3*128]
    hgemm_kernel<64, 128, true><<<ggrid, 256, SM0>>>(
        aggx, buf1, chr_W0, slv_W0, FEAT, 0, ENS * DIM, DIM);
    // 3) t1 = h0 @ W1 -> buf2 fp16 [N, 3*128]
    hgemm_kernel<128, 128, false><<<ggrid, 256, SM1>>>(
        buf1, buf2, chr_W1, slv_W1, ENS * DIM, DIM, ENS * DIM, DIM);
    // 4) agg1 = relu(A t1) -> buf1 fp16 [N, 3*128]
    gather384h_kernel<<<NTOT / 8, 256>>>(buf2, buf1);
    // 5) t2 = agg1 @ W2 -> buf2 fp16 [N, 3*64]
    hgemm_kernel<128, 64, false><<<ggrid, 256, SM2>>>(
        buf1, buf2, chr_W2, slv_W2, ENS * DIM, DIM, ENS * HALF, HALF);
    // 6) pool[batch] += relu(A t2)   (fused aggregation + relu + pool)
    gather192h_pool_kernel<<<NTOT / 8, 256>>>(buf2, chr_b, slv_b);
    // 7) head
    head_kernel<<<B, 128>>>(cfcW, cfcb, sfcW, sfcb, fc1W, fc1b, fc2W, fc2b, out);
}

// round 7
// speedup vs baseline: 4.0542x; 1.2849x over previous
#include <cuda_runtime.h>
#include <cuda_bf16.h>
#include <cuda_fp16.h>

// ---------------- problem constants ----------------
constexpr int N_CHR = 50000, E_CHR = 500000;
constexpr int N_SLV = 30000, E_SLV = 300000;
constexpr int NTOT = N_CHR + N_SLV;      // 80000
constexpr int ETOT = E_CHR + E_SLV;      // 800000
constexpr int B    = 256;
constexpr int FEAT = 64;
constexpr int DIM  = 128;
constexpr int HALF = 64;
constexpr int ENS  = 3;
constexpr int SCAN_BLK = 1024;
constexpr int NB_SCAN = (NTOT + SCAN_BLK - 1) / SCAN_BLK;  // 79

// ---------------- scratch (device globals; no allocations allowed) --------
__device__ __align__(128) __half g_aggx[(size_t)NTOT * FEAT];
__device__ __align__(128) __half g_buf1[(size_t)NTOT * ENS * DIM];   // h0 / agg1
__device__ __align__(128) __half g_buf2[(size_t)NTOT * ENS * DIM];   // t1 / t2
__device__ float g_pool[(size_t)B * 2 * ENS * HALF];
__device__ int   g_deg[NTOT];        // ZERO at entry of every run (static init + re-zero in gather64)
__device__ int   g_incl[NTOT];
__device__ int   g_off[NTOT];
__device__ int   g_cursor[NTOT];     // after fill: end offset of each node
__device__ int   g_csr[ETOT];
__device__ int   g_bsumx[128];

// ---------------- helpers ----------------
__device__ __forceinline__ void red_add_v4(float* p, float4 v) {
    asm volatile("red.global.add.v4.f32 [%0], {%1,%2,%3,%4};"
                 :: "l"(p), "f"(v.x), "f"(v.y), "f"(v.z), "f"(v.w)
                 : "memory");
}

__device__ __forceinline__ void edge_sd(int e, const int* __restrict__ ec,
                                        const int* __restrict__ es, int& src, int& dst) {
    if (e < E_CHR) { src = ec[e]; dst = ec[E_CHR + e]; }
    else { int e2 = e - E_CHR; src = N_CHR + es[e2]; dst = N_CHR + es[E_SLV + e2]; }
}

__device__ __forceinline__ void ldsm_x4(unsigned* r, unsigned addr) {
    asm volatile("ldmatrix.sync.aligned.m8n8.x4.shared.b16 {%0,%1,%2,%3}, [%4];"
                 : "=r"(r[0]), "=r"(r[1]), "=r"(r[2]), "=r"(r[3]) : "r"(addr));
}
__device__ __forceinline__ void ldsm_x2t(unsigned* r, unsigned addr) {
    asm volatile("ldmatrix.sync.aligned.m8n8.x2.trans.shared.b16 {%0,%1}, [%2];"
                 : "=r"(r[0]), "=r"(r[1]) : "r"(addr));
}
__device__ __forceinline__ void mma16816(float* d, const unsigned* a, const unsigned* b) {
    asm volatile("mma.sync.aligned.m16n8k16.row.col.f32.f16.f16.f32 "
                 "{%0,%1,%2,%3}, {%4,%5,%6,%7}, {%8,%9}, {%0,%1,%2,%3};"
                 : "+f"(d[0]), "+f"(d[1]), "+f"(d[2]), "+f"(d[3])
                 : "r"(a[0]), "r"(a[1]), "r"(a[2]), "r"(a[3]), "r"(b[0]), "r"(b[1]));
}
__device__ __forceinline__ void cp_async16z(unsigned sa, const void* g, bool v) {
    int sz = v ? 16 : 0;
    asm volatile("cp.async.cg.shared.global [%0], [%1], 16, %2;"
                 :: "r"(sa), "l"(g), "r"(sz) : "memory");
}
__device__ __forceinline__ void cp_commit() {
    asm volatile("cp.async.commit_group;" ::: "memory");
}
__device__ __forceinline__ void cp_wait1() {
    asm volatile("cp.async.wait_group 1;" ::: "memory");
}

// ---------------- CSR build ----------------
// also zeroes g_pool; requires g_deg == 0 at entry (maintained by gather64).
__global__ void count_deg_kernel(const int* __restrict__ ec, const int* __restrict__ es) {
    int e = blockIdx.x * blockDim.x + threadIdx.x;
    if (e < B * 384 / 4) ((float4*)g_pool)[e] = make_float4(0.f, 0.f, 0.f, 0.f);
    if (e >= ETOT) return;
    int src, dst; edge_sd(e, ec, es, src, dst);
    atomicAdd(&g_deg[dst], 1);
}

__global__ void scan1_kernel(int* __restrict__ bsum_raw) {
    __shared__ int s[SCAN_BLK];
    int tid = threadIdx.x;
    int i = blockIdx.x * SCAN_BLK + tid;
    int v = (i < NTOT) ? g_deg[i] : 0;
    s[tid] = v;
    __syncthreads();
    #pragma unroll
    for (int off = 1; off < SCAN_BLK; off <<= 1) {
        int t = (tid >= off) ? s[tid - off] : 0;
        __syncthreads();
        s[tid] += t;
        __syncthreads();
    }
    if (i < NTOT) g_incl[i] = s[tid];
    if (tid == SCAN_BLK - 1) bsum_raw[blockIdx.x] = s[tid];
}

__global__ void scan2_kernel(const int* __restrict__ bsum_raw) {
    __shared__ int s[128];
    int tid = threadIdx.x;
    int v = (tid < NB_SCAN) ? bsum_raw[tid] : 0;
    s[tid] = v;
    __syncthreads();
    #pragma unroll
    for (int off = 1; off < 128; off <<= 1) {
        int t = (tid >= off) ? s[tid - off] : 0;
        __syncthreads();
        s[tid] += t;
        __syncthreads();
    }
    g_bsumx[tid] = s[tid] - v;  // exclusive
}

__global__ void scan3_kernel() {
    int i = blockIdx.x * blockDim.x + threadIdx.x;
    if (i >= NTOT) return;
    int start = g_incl[i] - g_deg[i] + g_bsumx[i / SCAN_BLK];
    g_off[i] = start;
    g_cursor[i] = start;
}

__global__ void fill_csr_kernel(const int* __restrict__ ec, const int* __restrict__ es) {
    int e = blockIdx.x * blockDim.x + threadIdx.x;
    if (e >= ETOT) return;
    int src, dst; edge_sd(e, ec, es, src, dst);
    int pos = atomicAdd(&g_cursor[dst], 1);
    g_csr[pos] = src;
}

// ---------------- gathers ----------------
// first aggregation over raw fp32 features -> fp16 output; 2 nodes per warp.
// Software-prefetched; also re-zeroes g_deg for the next run.
__global__ __launch_bounds__(256)
void gather64_kernel(const float* __restrict__ xchr, const float* __restrict__ xslv,
                     __half* __restrict__ out) {
    int lane = threadIdx.x & 31;
    int sub = lane >> 4;
    int l = lane & 15;
    unsigned hmask = 0xffffu << (sub * 16);
    int node = ((blockIdx.x * blockDim.x + threadIdx.x) >> 5) * 2 + sub;
    if (node >= NTOT) return;
    int start = g_off[node], deg = g_cursor[node] - start;
    if (l == 0) g_deg[node] = 0;
    float4 a = make_float4(0.f, 0.f, 0.f, 0.f);
    for (int kb = 0; kb < deg; kb += 16) {
        int idx = (kb + l < deg) ? g_csr[start + kb + l] : 0;
        int m = min(16, deg - kb);
        int s = __shfl_sync(hmask, idx, 0, 16);
        const float4* sr = (s < N_CHR) ? (const float4*)(xchr + (size_t)s * 64)
                                       : (const float4*)(xslv + (size_t)(s - N_CHR) * 64);
        float4 p = sr[l];
        for (int k = 0; k < m; k++) {
            float4 c = p;
            if (k + 1 < m) {
                int s2 = __shfl_sync(hmask, idx, k + 1, 16);
                const float4* nr = (s2 < N_CHR) ? (const float4*)(xchr + (size_t)s2 * 64)
                                                : (const float4*)(xslv + (size_t)(s2 - N_CHR) * 64);
                p = nr[l];
            }
            a.x += c.x; a.y += c.y; a.z += c.z; a.w += c.w;
        }
    }
    __half2 h0 = __floats2half2_rn(a.x, a.y);
    __half2 h1 = __floats2half2_rn(a.z, a.w);
    uint2 u; u.x = *(unsigned*)&h0; u.y = *(unsigned*)&h1;
    *(uint2*)(out + (size_t)node * 64 + l * 4) = u;
}

__device__ __forceinline__ void acc8(float* a, uint4 v) {
    float2 f0 = __half22float2(*(__half2*)&v.x);
    float2 f1 = __half22float2(*(__half2*)&v.y);
    float2 f2 = __half22float2(*(__half2*)&v.z);
    float2 f3 = __half22float2(*(__half2*)&v.w);
    a[0] += f0.x; a[1] += f0.y; a[2] += f1.x; a[3] += f1.y;
    a[4] += f2.x; a[5] += f2.y; a[6] += f3.x; a[7] += f3.y;
}
__device__ __forceinline__ unsigned pack2r(float x, float y) {
    __half2 h = __floats2half2_rn(fmaxf(x, 0.f), fmaxf(y, 0.f));
    return *(unsigned*)&h;
}

// 384-wide aggregation over fp16 rows -> relu -> fp16 output. 2 nodes/warp.
__global__ __launch_bounds__(256)
void gather384h_kernel(const __half* __restrict__ in, __half* __restrict__ out) {
    int lane = threadIdx.x & 31;
    int sub = lane >> 4;
    int l = lane & 15;
    unsigned hmask = 0xffffu << (sub * 16);
    int node = ((blockIdx.x * blockDim.x + threadIdx.x) >> 5) * 2 + sub;
    if (node >= NTOT) return;
    int start = g_off[node], deg = g_cursor[node] - start;
    float a[24];
    #pragma unroll
    for (int i = 0; i < 24; i++) a[i] = 0.f;
    for (int kb = 0; kb < deg; kb += 16) {
        int idx = (kb + l < deg) ? g_csr[start + kb + l] : 0;
        int m = min(16, deg - kb);
        int s = __shfl_sync(hmask, idx, 0, 16);
        const uint4* sr = (const uint4*)(in + (size_t)s * 384);
        uint4 p0 = sr[l], p1 = sr[l + 16], p2 = sr[l + 32];
        for (int k = 0; k < m; k++) {
            uint4 c0 = p0, c1 = p1, c2 = p2;
            if (k + 1 < m) {
                int s2 = __shfl_sync(hmask, idx, k + 1, 16);
                const uint4* nr = (const uint4*)(in + (size_t)s2 * 384);
                p0 = nr[l]; p1 = nr[l + 16]; p2 = nr[l + 32];
            }
            acc8(a, c0); acc8(a + 8, c1); acc8(a + 16, c2);
        }
    }
    uint4* orow = (uint4*)(out + (size_t)node * 384);
    uint4 o;
    o.x = pack2r(a[0], a[1]);  o.y = pack2r(a[2], a[3]);
    o.z = pack2r(a[4], a[5]);  o.w = pack2r(a[6], a[7]);
    orow[l] = o;
    o.x = pack2r(a[8], a[9]);  o.y = pack2r(a[10], a[11]);
    o.z = pack2r(a[12], a[13]); o.w = pack2r(a[14], a[15]);
    orow[l + 16] = o;
    o.x = pack2r(a[16], a[17]); o.y = pack2r(a[18], a[19]);
    o.z = pack2r(a[20], a[21]); o.w = pack2r(a[22], a[23]);
    orow[l + 32] = o;
}

__device__ __forceinline__ void acc4(float* a, uint2 v) {
    float2 f0 = __half22float2(*(__half2*)&v.x);
    float2 f1 = __half22float2(*(__half2*)&v.y);
    a[0] += f0.x; a[1] += f0.y; a[2] += f1.x; a[3] += f1.y;
}

// layer-2 aggregation (192-wide fp16 rows) + relu + global_add_pool. 2 nodes/warp.
__global__ __launch_bounds__(256)
void gather192h_pool_kernel(const __half* __restrict__ in,
                            const int* __restrict__ bchr, const int* __restrict__ bslv) {
    int lane = threadIdx.x & 31;
    int sub = lane >> 4;
    int l = lane & 15;
    unsigned hmask = 0xffffu << (sub * 16);
    int node = ((blockIdx.x * blockDim.x + threadIdx.x) >> 5) * 2 + sub;
    if (node >= NTOT) return;
    int start = g_off[node], deg = g_cursor[node] - start;
    float a[12];
    #pragma unroll
    for (int i = 0; i < 12; i++) a[i] = 0.f;
    for (int kb = 0; kb < deg; kb += 16) {
        int idx = (kb + l < deg) ? g_csr[start + kb + l] : 0;
        int m = min(16, deg - kb);
        int s = __shfl_sync(hmask, idx, 0, 16);
        const uint2* sr = (const uint2*)(in + (size_t)s * 192);
        uint2 p0 = sr[l], p1 = sr[l + 16], p2 = sr[l + 32];
        for (int k = 0; k < m; k++) {
            uint2 c0 = p0, c1 = p1, c2 = p2;
            if (k + 1 < m) {
                int s2 = __shfl_sync(hmask, idx, k + 1, 16);
                const uint2* nr = (const uint2*)(in + (size_t)s2 * 192);
                p0 = nr[l]; p1 = nr[l + 16]; p2 = nr[l + 32];
            }
            acc4(a, c0); acc4(a + 4, c1); acc4(a + 8, c2);
        }
    }
    #pragma unroll
    for (int i = 0; i < 12; i++) a[i] = fmaxf(a[i], 0.f);
    int b, colbase;
    if (node < N_CHR) { b = bchr[node]; colbase = 0; }
    else              { b = bslv[node - N_CHR]; colbase = 192; }
    float* prow = g_pool + (size_t)b * 384 + colbase;
    red_add_v4(prow + l * 4,        make_float4(a[0], a[1], a[2], a[3]));
    red_add_v4(prow + 64 + l * 4,   make_float4(a[4], a[5], a[6], a[7]));
    red_add_v4(prow + 128 + l * 4,  make_float4(a[8], a[9], a[10], a[11]));
}

// ---------------- fp16 tensor-core GEMM (cp.async double-buffered) --------
// out[n, e*out_eoff + j] = (relu?)( in[n, e*in_eoff + 0:K] @ W[e] )
template<int K, int MOUT, bool RELU_OUT>
__global__ __launch_bounds__(256, 1)
void hgemm_kernel(const __half* __restrict__ in, __half* __restrict__ out,
                  const float* __restrict__ Wc, const float* __restrict__ Ws,
                  int in_stride, int in_eoff, int out_stride, int out_eoff) {
    constexpr int TR = 128;
    constexpr int CGS = MOUT / 64;          // col groups (1 or 2)
    constexpr int RGS = 8 / CGS;            // row groups
    constexpr int WM = TR / RGS;            // warp rows (32 or 16)
    constexpr int MT = WM / 16;             // m-tiles per warp (2 or 1)
    constexpr int LDA = K + 8;
    constexpr int LDB = MOUT + 8;
    constexpr int KS = K / 16;
    constexpr int ABUF = TR * LDA;          // halves per A buffer

    extern __shared__ __half hsm[];
    __half* sA = hsm;                       // [2][TR][LDA]
    __half* sB = hsm + 2 * ABUF;            // [K][LDB]

    const int e = blockIdx.y;
    const int branch = blockIdx.z;
    const int tid = threadIdx.x;
    const int wid = tid >> 5;
    const int lane = tid & 31;
    const int rowgrp = wid / CGS;
    const int colgrp = wid % CGS;

    const int base  = branch ? N_CHR : 0;
    const int nrows = branch ? N_SLV : N_CHR;
    const int ntiles = (nrows + TR - 1) / TR;
    const float* W = (branch ? Ws : Wc) + (size_t)e * K * MOUT;

    // weights fp32 -> fp16 smem [k][n]
    for (int idx = tid; idx < K * MOUT / 4; idx += 256) {
        int k = idx / (MOUT / 4), c = idx % (MOUT / 4);
        float4 w = ((const float4*)W)[idx];
        __half2 h0 = __floats2half2_rn(w.x, w.y);
        __half2 h1 = __floats2half2_rn(w.z, w.w);
        uint2 u; u.x = *(unsigned*)&h0; u.y = *(unsigned*)&h1;
        *(uint2*)(sB + k * LDB + c * 4) = u;
    }

    unsigned sa_base = (unsigned)__cvta_generic_to_shared(sA);
    unsigned sb_base = (unsigned)__cvta_generic_to_shared(sB);

    auto load_tile = [&](int t, int buf) {
        int row0 = base + t * TR;
        constexpr int C8 = TR * (K / 8);
        for (int i = tid; i < C8; i += 256) {
            int r = i / (K / 8), c = i % (K / 8);
            bool valid = (row0 + r) < base + nrows;
            int rr = valid ? (row0 + r) : base;
            const void* g = in + (size_t)rr * in_stride + (size_t)e * in_eoff + c * 8;
            cp_async16z(sa_base + (unsigned)(buf * ABUF + r * LDA + c * 8) * 2, g, valid);
        }
    };

    int t0 = blockIdx.x;
    if (t0 < ntiles) load_tile(t0, 0);
    cp_commit();

    int bi = 0;
    for (int t = t0; t < ntiles; t += gridDim.x, bi ^= 1) {
        int tn = t + gridDim.x;
        if (tn < ntiles) load_tile(tn, bi ^ 1);
        cp_commit();
        cp_wait1();
        __syncthreads();

        int row0 = base + t * TR;
        int rcnt = min(TR, base + nrows - row0);
        unsigned abuf = sa_base + (unsigned)(bi * ABUF) * 2;

        float acc[MT][8][4];
        #pragma unroll
        for (int mt = 0; mt < MT; mt++)
            #pragma unroll
            for (int nt = 0; nt < 8; nt++)
                #pragma unroll
                for (int q = 0; q < 4; q++) acc[mt][nt][q] = 0.f;

        #pragma unroll
        for (int ks = 0; ks < KS; ks++) {
            unsigned a[MT][4];
            #pragma unroll
            for (int mt = 0; mt < MT; mt++) {
                int r = rowgrp * WM + mt * 16 + (lane & 15);
                int c = ks * 16 + (lane >> 4) * 8;
                ldsm_x4(a[mt], abuf + (unsigned)(r * LDA + c) * 2);
            }
            #pragma unroll
            for (int nt = 0; nt < 8; nt++) {
                unsigned b[2];
                int rk = ks * 16 + (lane & 15);
                int cn = colgrp * 64 + nt * 8;
                ldsm_x2t(b, sb_base + (unsigned)(rk * LDB + cn) * 2);
                #pragma unroll
                for (int mt = 0; mt < MT; mt++)
                    mma16816(acc[mt][nt], a[mt], b);
            }
        }

        // epilogue: fp16 (+relu) stores
        int lrow = lane >> 2, lcol = (lane & 3) * 2;
        #pragma unroll
        for (int mt = 0; mt < MT; mt++) {
            #pragma unroll
            for (int nt = 0; nt < 8; nt++) {
                int col = colgrp * 64 + nt * 8 + lcol;
                int r1 = rowgrp * WM + mt * 16 + lrow;
                float x0 = acc[mt][nt][0], x1 = acc[mt][nt][1];
                float x2 = acc[mt][nt][2], x3 = acc[mt][nt][3];
                if (RELU_OUT) {
                    x0 = fmaxf(x0, 0.f); x1 = fmaxf(x1, 0.f);
                    x2 = fmaxf(x2, 0.f); x3 = fmaxf(x3, 0.f);
                }
                if (r1 < rcnt) {
                    __half2 h = __floats2half2_rn(x0, x1);
                    *(__half2*)(out + (size_t)(row0 + r1) * out_stride + (size_t)e * out_eoff + col) = h;
                }
                if (r1 + 8 < rcnt) {
                    __half2 h = __floats2half2_rn(x2, x3);
                    *(__half2*)(out + (size_t)(row0 + r1 + 8) * out_stride + (size_t)e * out_eoff + col) = h;
                }
            }
        }
        __syncthreads();
    }
}

// ---------------- head: projection heads + concat + fc1 + fc2 -------------
__global__ __launch_bounds__(128)
void head_kernel(const float* __restrict__ cfcW, const float* __restrict__ cfcb,
                 const float* __restrict__ sfcW, const float* __restrict__ sfcb,
                 const float* __restrict__ fc1W, const float* __restrict__ fc1b,
                 const float* __restrict__ fc2W, const float* __restrict__ fc2b,
                 float* __restrict__ out) {
    __shared__ float sPool[384];
    __shared__ float sHg[768];
    __shared__ float sRed[128];
    const int b = blockIdx.x;
    const int tid = threadIdx.x;

    for (int i = tid; i < 384; i += 128) sPool[i] = g_pool[(size_t)b * 384 + i];
    __syncthreads();

    #pragma unroll
    for (int p = 0; p < 6; p++) {
        const bool slv = (p >= 3);
        const int e = slv ? (p - 3) : p;
        const float* W = slv ? sfcW : cfcW;
        const float* bias = slv ? sfcb : cfcb;
        const float* rep = sPool + (slv ? 192 : 0) + e * HALF;
        float acc = bias[e * DIM + tid];
        #pragma unroll 8
        for (int k = 0; k < HALF; k++)
            acc = fmaf(rep[k], W[(size_t)e * HALF * DIM + k * DIM + tid], acc);
        sHg[p * DIM + tid] = fmaxf(acc, 0.f);
    }
    __syncthreads();

    float acc = fc1b[tid];
    #pragma unroll 8
    for (int h = 0; h < 768; h++)
        acc = fmaf(sHg[h], fc1W[(size_t)h * DIM + tid], acc);
    float o1 = fmaxf(acc, 0.f);

    sRed[tid] = o1 * fc2W[tid];
    __syncthreads();
    if (tid < 64) sRed[tid] += sRed[tid + 64];
    __syncthreads();
    if (tid < 32) {
        float x = sRed[tid] + sRed[tid + 32];
        #pragma unroll
        for (int o = 16; o; o >>= 1) x += __shfl_down_sync(0xffffffffu, x, o);
        if (tid == 0) out[b] = x + fc2b[0];
    }
}

// ---------------- launch ----------------
extern "C" void kernel_launch(void* const* d_in, const int* in_sizes, int n_in,
                              void* d_out, int out_size) {
    const float* chr_x  = (const float*)d_in[0];
    const float* slv_x  = (const float*)d_in[1];
    const int*   chr_ei = (const int*)d_in[2];
    const int*   slv_ei = (const int*)d_in[3];
    const int*   chr_b  = (const int*)d_in[4];
    const int*   slv_b  = (const int*)d_in[5];
    const float* chr_W0 = (const float*)d_in[6];
    const float* chr_W1 = (const float*)d_in[7];
    const float* chr_W2 = (const float*)d_in[8];
    const float* slv_W0 = (const float*)d_in[9];
    const float* slv_W1 = (const float*)d_in[10];
    const float* slv_W2 = (const float*)d_in[11];
    const float* cfcW   = (const float*)d_in[12];
    const float* cfcb   = (const float*)d_in[13];
    const float* sfcW   = (const float*)d_in[14];
    const float* sfcb   = (const float*)d_in[15];
    const float* fc1W   = (const float*)d_in[16];
    const float* fc1b   = (const float*)d_in[17];
    const float* fc2W   = (const float*)d_in[18];
    const float* fc2b   = (const float*)d_in[19];
    float* out = (float*)d_out;

    __half *aggx, *buf1, *buf2;
    int* csr;
    cudaGetSymbolAddress((void**)&aggx, g_aggx);
    cudaGetSymbolAddress((void**)&buf1, g_buf1);
    cudaGetSymbolAddress((void**)&buf2, g_buf2);
    cudaGetSymbolAddress((void**)&csr, g_csr);

    // dynamic smem: 2*TR*LDA + K*LDB halves
    constexpr int SM0 = (2 * 128 * 72  + 64  * 136) * 2;  // 54272
    constexpr int SM1 = (2 * 128 * 136 + 128 * 136) * 2;  // 104448
    constexpr int SM2 = (2 * 128 * 136 + 128 * 72)  * 2;  // 88064
    cudaFuncSetAttribute((const void*)hgemm_kernel<64, 128, true>,
                         cudaFuncAttributeMaxDynamicSharedMemorySize, SM0);
    cudaFuncSetAttribute((const void*)hgemm_kernel<128, 128, false>,
                         cudaFuncAttributeMaxDynamicSharedMemorySize, SM1);
    cudaFuncSetAttribute((const void*)hgemm_kernel<128, 64, false>,
                         cudaFuncAttributeMaxDynamicSharedMemorySize, SM2);

    dim3 ggrid(50, ENS, 2);  // ~8 tiles per block -> cp.async pipeline active

    // ---- CSR build (g_deg zero at entry; re-zeroed inside gather64) ----
    count_deg_kernel<<<(ETOT + 255) / 256, 256>>>(chr_ei, slv_ei);   // + pool zero
    scan1_kernel<<<NB_SCAN, SCAN_BLK>>>(csr + ETOT - 128);  // raw block sums in csr tail
    scan2_kernel<<<1, 128>>>(csr + ETOT - 128);
    scan3_kernel<<<(NTOT + 255) / 256, 256>>>();
    fill_csr_kernel<<<(ETOT + 255) / 256, 256>>>(chr_ei, slv_ei);

    // ---- forward pass ----
    // 1) aggx = A x -> fp16 [N,64]
    gather64_kernel<<<(NTOT / 2 + 7) / 8, 256>>>(chr_x, slv_x, aggx);
    // 2) h0 = relu(aggx @ W0) -> buf1 fp16 [N, 3*128]
    hgemm_kernel<64, 128, true><<<ggrid, 256, SM0>>>(
        aggx, buf1, chr_W0, slv_W0, FEAT, 0, ENS * DIM, DIM);
    // 3) t1 = h0 @ W1 -> buf2 fp16 [N, 3*128]
    hgemm_kernel<128, 128, false><<<ggrid, 256, SM1>>>(
        buf1, buf2, chr_W1, slv_W1, ENS * DIM, DIM, ENS * DIM, DIM);
    // 4) agg1 = relu(A t1) -> buf1 fp16 [N, 3*128]
    gather384h_kernel<<<(NTOT / 2 + 7) / 8, 256>>>(buf2, buf1);
    // 5) t2 = agg1 @ W2 -> buf2 fp16 [N, 3*64]
    hgemm_kernel<128, 64, false><<<ggrid, 256, SM2>>>(
        buf1, buf2, chr_W2, slv_W2, ENS * DIM, DIM, ENS * HALF, HALF);
    // 6) pool[batch] += relu(A t2)   (fused aggregation + relu + pool)
    gather192h_pool_kernel<<<(NTOT / 2 + 7) / 8, 256>>>(buf2, chr_b, slv_b);
    // 7) head
    head_kernel<<<B, 128>>>(cfcW, cfcb, sfcW, sfcb, fc1W, fc1b, fc2W, fc2b, out);
}